// round 14
// baseline (speedup 1.0000x reference)
#include <cuda_runtime.h>
#include <cstdint>

#define BATCH 16384
#define DIM   2048
#define NEXP  64
#define BM    32
#define BK    32
#define NRB   (BATCH / BM)         // 512 row blocks
#define NCH   (DIM / BK)           // 64 k-chunks per row block
#define UNITS (NRB * NCH)          // 32768
#define NCTA  888                  // 148 SMs x 6 CTAs
#define UBASE (UNITS / NCTA)       // 36
#define UEXTRA (UNITS - UBASE * NCTA) // 800
#define NTH   128

#define X_BYTES (BM * BK * 4)             // 4096
#define W_BYTES (NEXP * BK * 4)           // 8192
#define STAGE_BYTES (X_BYTES + W_BYTES)   // 12288
#define SMEM_DYN (2 * STAGE_BYTES)        // 24576

__device__ float g_logits[BATCH][NEXP];   // zero-init; re-zeroed after use
__device__ int   g_done[NRB];             // zero-init; re-armed after use

__device__ __forceinline__ void ffma2(unsigned long long& acc,
                                      unsigned long long a,
                                      unsigned long long w) {
    asm("fma.rn.f32x2 %0, %1, %2, %0;" : "+l"(acc) : "l"(a), "l"(w));
}
__device__ __forceinline__ uint32_t smem_u32(const void* p) {
    uint32_t a;
    asm("{ .reg .u64 t; cvta.to.shared.u64 t, %1; cvt.u32.u64 %0, t; }"
        : "=r"(a) : "l"(p));
    return a;
}
#define CP_ASYNC16(dst, src)                                                  \
    asm volatile("cp.async.cg.shared.global [%0], [%1], 16;"                  \
                 :: "r"(dst), "l"(src) : "memory")
#define CP_COMMIT() asm volatile("cp.async.commit_group;" ::: "memory")
#define CP_WAIT1()  asm volatile("cp.async.wait_group 1;" ::: "memory")
#define CP_WAIT0()  asm volatile("cp.async.wait_group 0;" ::: "memory")

__global__ __launch_bounds__(NTH, 6)
void gate_kernel(const float* __restrict__ x,
                 const float* __restrict__ W,
                 const float* __restrict__ bias,
                 float* __restrict__ out) {
    extern __shared__ char dyn[];
    __shared__ int s_fin;

    const int tid  = threadIdx.x;
    const int w    = tid >> 5;            // warp 0..3, covers rows w*8..w*8+7
    const int lane = tid & 31;
    const int pg   = lane >> 3;           // 0..3
    const int el   = lane & 7;            // 0..7

    const uint32_t dynb = smem_u32(dyn);

    // per-thread operand base offsets (XOR-swizzled smem layout)
    const int r0 = w * 8 + pg;            // rows within 32-row tile
    const int r1 = r0 + 4;
    const uint32_t abase0 = r0 * 128 + (pg << 4);
    const uint32_t abase1 = r1 * 128 + ((pg + 4) << 4);
    const uint32_t wbase  = el * 144;     // el*128 + (el<<4)

    // work range: contiguous units, unit = (rb, chunk)
    const int cta = blockIdx.x;
    const int u0  = cta * UBASE + (cta < UEXTRA ? cta : UEXTRA);
    const int cnt = UBASE + (cta < UEXTRA ? 1 : 0);

    // acc[i][j]: row (rb*32 + w*8 + pg + 4*i), expert el+8*j; .x even-k, .y odd-k
    unsigned long long acc[2][8];
    #pragma unroll
    for (int i = 0; i < 2; i++)
        #pragma unroll
        for (int j = 0; j < 8; j++) acc[i][j] = 0ull;

#define PRE(u, st)                                                             \
    {                                                                          \
        const int rbp = (u) >> 6, chp = (u) & 63;                              \
        const float* xb = x + (size_t)(rbp * BM) * DIM + chp * BK;             \
        const float* wb = W + chp * BK;                                        \
        _Pragma("unroll")                                                      \
        for (int s = 0; s < 2; s++) {                                          \
            int idx = s * NTH + tid;          /* 0..255 */                     \
            int r = idx >> 3, k4 = idx & 7;                                    \
            uint32_t dst = dynb + (st) * STAGE_BYTES + r * 128                 \
                         + ((k4 ^ (r & 7)) << 4);                              \
            CP_ASYNC16(dst, xb + (size_t)r * DIM + k4 * 4);                    \
        }                                                                      \
        _Pragma("unroll")                                                      \
        for (int s = 0; s < 4; s++) {                                          \
            int idx = s * NTH + tid;          /* 0..511 */                     \
            int e = idx >> 3, k4 = idx & 7;                                    \
            uint32_t dst = dynb + (st) * STAGE_BYTES + X_BYTES + e * 128       \
                         + ((k4 ^ (e & 7)) << 4);                              \
            CP_ASYNC16(dst, wb + (size_t)e * DIM + k4 * 4);                    \
        }                                                                      \
        CP_COMMIT();                                                           \
    }

#define FLUSH(rbv, nchv)                                                       \
    {                                                                          \
        _Pragma("unroll")                                                      \
        for (int j = 0; j < 8; j++) {                                          \
            int e = el + 8 * j;                                                \
            float2 v0 = *(float2*)&acc[0][j];                                  \
            float2 v1 = *(float2*)&acc[1][j];                                  \
            atomicAdd(&g_logits[(rbv) * BM + r0][e], v0.x + v0.y);             \
            atomicAdd(&g_logits[(rbv) * BM + r1][e], v1.x + v1.y);             \
            acc[0][j] = 0ull; acc[1][j] = 0ull;                                \
        }                                                                      \
        __threadfence();                                                       \
        __syncthreads();                                                       \
        if (tid == 0) {                                                        \
            int old = atomicAdd(&g_done[rbv], (nchv));                         \
            s_fin = (old + (nchv) == NCH);                                     \
        }                                                                      \
        __syncthreads();                                                       \
        if (s_fin) {                                                           \
            __threadfence();                                                   \
            if (tid < BM) {                                                    \
                const int row = (rbv) * BM + tid;                              \
                float l1 = -1e30f, l2 = -1e30f;                                \
                int   i1 = 0,      i2 = 0;                                     \
                _Pragma("unroll")                                              \
                for (int e4 = 0; e4 < NEXP / 4; e4++) {                        \
                    float4 p = __ldcg((const float4*)&g_logits[row][4 * e4]);  \
                    float4 b4 = __ldg(&((const float4*)bias)[e4]);             \
                    float v[4] = {p.x + b4.x, p.y + b4.y,                      \
                                  p.z + b4.z, p.w + b4.w};                     \
                    _Pragma("unroll")                                          \
                    for (int c = 0; c < 4; c++) {                              \
                        int e = 4 * e4 + c;                                    \
                        if (v[c] > l1) { l2 = l1; i2 = i1; l1 = v[c]; i1 = e; }\
                        else if (v[c] > l2) { l2 = v[c]; i2 = e; }             \
                    }                                                          \
                }                                                              \
                float e2 = expf(l2 - l1);                                      \
                float dn = 1.0f + e2;                                          \
                out[2 * row]                 = 1.0f / dn;                      \
                out[2 * row + 1]             = e2 / dn;                        \
                out[2 * BATCH + 2 * row]     = (float)i1;                      \
                out[2 * BATCH + 2 * row + 1] = (float)i2;                      \
                float4 z = make_float4(0.f, 0.f, 0.f, 0.f);                    \
                _Pragma("unroll")                                              \
                for (int e4 = 0; e4 < NEXP / 4; e4++)                          \
                    *(float4*)&g_logits[row][4 * e4] = z;                      \
            }                                                                  \
            if (tid == 0) g_done[rbv] = 0;                                     \
        }                                                                      \
    }

    int cur_rb = u0 >> 6;
    int nacc   = 0;

    PRE(u0, 0);

    for (int k = 0; k < cnt; k++) {
        const int u  = u0 + k;
        const int rb = u >> 6;
        if (rb != cur_rb) {
            FLUSH(cur_rb, nacc);
            cur_rb = rb;
            nacc = 0;
        }
        __syncthreads();                        // safe to overwrite next buf
        if (k + 1 < cnt) PRE(u0 + k + 1, (k + 1) & 1);
        if (k + 1 < cnt) { CP_WAIT1(); } else { CP_WAIT0(); }
        __syncthreads();                        // current buf visible

        const char* sb = dyn + (k & 1) * STAGE_BYTES;
        #pragma unroll
        for (int kf4 = 0; kf4 < 8; kf4++) {
            const uint32_t sw = kf4 << 4;
            ulonglong2 a0 = *(const ulonglong2*)(sb + (abase0 ^ sw));
            ulonglong2 a1 = *(const ulonglong2*)(sb + (abase1 ^ sw));
            #pragma unroll
            for (int jb = 0; jb < 2; jb++) {
                ulonglong2 w4[4];
                #pragma unroll
                for (int jj = 0; jj < 4; jj++) {
                    uint32_t off = (wbase + (jb * 4 + jj) * 1024) ^ sw;
                    w4[jj] = *(const ulonglong2*)(sb + X_BYTES + off);
                }
                #pragma unroll
                for (int jj = 0; jj < 4; jj++) {
                    int j = jb * 4 + jj;
                    ffma2(acc[0][j], a0.x, w4[jj].x);
                    ffma2(acc[0][j], a0.y, w4[jj].y);
                    ffma2(acc[1][j], a1.x, w4[jj].x);
                    ffma2(acc[1][j], a1.y, w4[jj].y);
                }
            }
        }
        nacc++;
    }
    FLUSH(cur_rb, nacc);
}

extern "C" void kernel_launch(void* const* d_in, const int* in_sizes, int n_in,
                              void* d_out, int out_size) {
    const float* x = (const float*)d_in[0];
    const float* W = (const float*)d_in[1];
    const float* b = (const float*)d_in[2];
    float* out = (float*)d_out;
    (void)in_sizes; (void)n_in; (void)out_size;
    gate_kernel<<<NCTA, NTH, SMEM_DYN>>>(x, W, b, out);
}

// round 17
// speedup vs baseline: 1.5756x; 1.5756x over previous
#include <cuda_runtime.h>
#include <cstdint>

#define BATCH 16384
#define DIM   2048
#define NEXP  64
#define BM    64
#define BK    32
#define KSPLIT 4
#define KPER  (DIM / KSPLIT)     // 512
#define NTILES (KPER / BK)       // 16
#define NTHREADS 128
#define XS_STR 132
#define WS_STR 34
#define LG_STR 68

// 16MB scratch for split-K partial logits: [split][row][expert]
__device__ float g_part[KSPLIT][BATCH][NEXP];
__device__ int   g_cnt[BATCH / BM];          // zero-init; re-armed after use

// Packed dual-fp32 FMA (FFMA2). Only reachable via PTX fma.rn.f32x2.
__device__ __forceinline__ void ffma2(unsigned long long& acc,
                                      unsigned long long a,
                                      unsigned long long w) {
    asm("fma.rn.f32x2 %0, %1, %2, %0;" : "+l"(acc) : "l"(a), "l"(w));
}
__device__ __forceinline__ unsigned long long dup2(float v) {
    float2 d = make_float2(v, v);
    return *(unsigned long long*)&d;
}
__device__ __forceinline__ unsigned long long pack2(float a, float b) {
    float2 d = make_float2(a, b);
    return *(unsigned long long*)&d;
}

union __align__(16) Smem {
    struct {
        float xs[BK / 2][XS_STR];   // interleaved row-pair x tile
        float ws[NEXP][WS_STR];     // W tile, row-major [expert][k]
    } g;
    float logits[BM][LG_STR];       // epilogue staging
};

__global__ __launch_bounds__(NTHREADS)
void gate_kernel(const float* __restrict__ x,
                 const float* __restrict__ W,
                 const float* __restrict__ bias,
                 float* __restrict__ out) {
    __shared__ Smem sm;
    __shared__ int s_last;
    const int tid  = threadIdx.x;
    const int rb   = blockIdx.x;
    const int row0 = rb * BM;
    const int ks   = blockIdx.y;          // k-split id
    const int kbase = ks * KPER;
    const int ty   = tid >> 4;            // 0..7 : 8 rows (4 pairs)
    const int tx   = tid & 15;            // 0..15: experts {tx,16+tx,32+tx,48+tx}

    unsigned long long acc[4][4];
    #pragma unroll
    for (int p = 0; p < 4; p++)
        #pragma unroll
        for (int j = 0; j < 4; j++) acc[p][j] = 0ull;

    const int kf2l = tid & 15;
    const int r2b  = tid >> 4;
    float2 xv[4][2];
    float2 wv[8];
    const float* xbase = x + (size_t)row0 * DIM + kbase;
    const float* wbase = W + kbase;

#define LOADT(t)                                                              \
    {                                                                         \
        const float* xp = xbase + (t) * BK + 2 * kf2l;                        \
        _Pragma("unroll")                                                     \
        for (int p = 0; p < 4; p++) {                                         \
            int r2 = r2b + 8 * p;                                             \
            xv[p][0] = *(const float2*)(xp + (size_t)(2 * r2) * DIM);         \
            xv[p][1] = *(const float2*)(xp + (size_t)(2 * r2 + 1) * DIM);     \
        }                                                                     \
        const float* wp = wbase + (t) * BK + 2 * kf2l;                        \
        _Pragma("unroll")                                                     \
        for (int p = 0; p < 8; p++) {                                         \
            int e = r2b + 8 * p;                                              \
            wv[p] = *(const float2*)(wp + (size_t)e * DIM);                   \
        }                                                                     \
    }

    LOADT(0);

    for (int t = 0; t < NTILES; t++) {
        __syncthreads();
        #pragma unroll
        for (int p = 0; p < 4; p++) {
            int r2 = r2b + 8 * p;
            float4 v = make_float4(xv[p][0].x, xv[p][1].x,
                                   xv[p][0].y, xv[p][1].y);
            *(float4*)&sm.g.xs[kf2l][4 * r2] = v;
        }
        #pragma unroll
        for (int p = 0; p < 8; p++) {
            int e = r2b + 8 * p;
            *(float2*)&sm.g.ws[e][2 * kf2l] = wv[p];
        }
        __syncthreads();

        if (t + 1 < NTILES) LOADT(t + 1);

        #pragma unroll
        for (int kf2 = 0; kf2 < BK / 2; kf2++) {
            float4 a[4];
            #pragma unroll
            for (int p = 0; p < 4; p++)
                a[p] = *(const float4*)&sm.g.xs[kf2][(ty * 4 + p) * 4];
            float2 w2[4];
            #pragma unroll
            for (int j = 0; j < 4; j++)
                w2[j] = *(const float2*)&sm.g.ws[16 * j + tx][2 * kf2];
            #pragma unroll
            for (int j = 0; j < 4; j++) {
                unsigned long long w0 = dup2(w2[j].x);
                unsigned long long w1 = dup2(w2[j].y);
                #pragma unroll
                for (int p = 0; p < 4; p++) {
                    ffma2(acc[p][j], pack2(a[p].x, a[p].y), w0);
                    ffma2(acc[p][j], pack2(a[p].z, a[p].w), w1);
                }
            }
        }
    }

    __syncthreads();   // smem becomes staging buffer

    // stage partial logits in smem for coalesced global writes
    #pragma unroll
    for (int j = 0; j < 4; j++) {
        int e = 16 * j + tx;
        #pragma unroll
        for (int p = 0; p < 4; p++) {
            float2 a = *(float2*)&acc[p][j];
            sm.logits[ty * 8 + 2 * p    ][e] = a.x;
            sm.logits[ty * 8 + 2 * p + 1][e] = a.y;
        }
    }
    __syncthreads();

    // coalesced store: thread t writes 8 float4 (row = t>>1, half = t&1)
    {
        const int r = tid >> 1;
        const int h = tid & 1;
        float* dst = &g_part[ks][row0 + r][h * 32];
        #pragma unroll
        for (int i = 0; i < 8; i++) {
            float4 v = *(const float4*)&sm.logits[r][h * 32 + 4 * i];
            *(float4*)(dst + 4 * i) = v;
        }
    }

    // ---- last CTA of this row block does the reduce + top2 + softmax ----
    if (tid == 0) {
        __threadfence();
        s_last = (atomicAdd(&g_cnt[rb], 1) == KSPLIT - 1);
    }
    __syncthreads();
    if (!s_last) return;
    __threadfence();

    if (tid < BM) {
        const int row = row0 + tid;
        float l1 = -1e30f, l2 = -1e30f;
        int   i1 = 0,      i2 = 0;
        #pragma unroll
        for (int e4 = 0; e4 < NEXP / 4; e4++) {
            float4 s = __ldcg((const float4*)&g_part[0][row][4 * e4]);
            #pragma unroll
            for (int kk = 1; kk < KSPLIT; kk++) {
                float4 p = __ldcg((const float4*)&g_part[kk][row][4 * e4]);
                s.x += p.x; s.y += p.y; s.z += p.z; s.w += p.w;
            }
            float4 bv = *(const float4*)&bias[4 * e4];
            float v[4] = {s.x + bv.x, s.y + bv.y, s.z + bv.z, s.w + bv.w};
            #pragma unroll
            for (int c = 0; c < 4; c++) {
                int e = 4 * e4 + c;
                if (v[c] > l1)      { l2 = l1; i2 = i1; l1 = v[c]; i1 = e; }
                else if (v[c] > l2) { l2 = v[c]; i2 = e; }
            }
        }
        float e2    = expf(l2 - l1);
        float denom = 1.0f + e2;
        out[2 * row]                 = 1.0f / denom;
        out[2 * row + 1]             = e2 / denom;
        out[2 * BATCH + 2 * row]     = (float)i1;
        out[2 * BATCH + 2 * row + 1] = (float)i2;
    }
    if (tid == 0) g_cnt[rb] = 0;    // re-arm for graph replay
}

extern "C" void kernel_launch(void* const* d_in, const int* in_sizes, int n_in,
                              void* d_out, int out_size) {
    const float* x = (const float*)d_in[0];
    const float* W = (const float*)d_in[1];
    const float* b = (const float*)d_in[2];
    float* out = (float*)d_out;
    (void)in_sizes; (void)n_in; (void)out_size;
    gate_kernel<<<dim3(BATCH / BM, KSPLIT), NTHREADS>>>(x, W, b, out);
}